// round 1
// baseline (speedup 1.0000x reference)
#include <cuda_runtime.h>
#include <cuda_bf16.h>

#define BATCH       32768
#define IN_CH       512
#define OUT_CH      1024
#define NP          17
#define NSTEPS      3

// total float4 elements of input
#define TOTAL4      (BATCH * IN_CH / 4)     // 4,194,304
#define THREADS     256

__device__ __forceinline__ float tanh_fast(float x) {
    // tanh(x) = 1 - 2/(exp(2x)+1); abs err ~1e-6 via __expf (MUFU EX2 path).
    // Saturates correctly: exp(2x)->inf => 1, exp(2x)->0 => -1.
    float e = __expf(2.0f * x);
    return 1.0f - 2.0f / (e + 1.0f);
}

__global__ void __launch_bounds__(THREADS)
macunit_kernel(const float4* __restrict__ data,
               const float*  __restrict__ angles,
               const float*  __restrict__ velocity,
               const float*  __restrict__ attention,
               const float*  __restrict__ coeff,
               const float*  __restrict__ bias,
               float4*       __restrict__ out)
{
    __shared__ float sV[NP];
    __shared__ float sA[NP];
    if (threadIdx.x < NP) {
        sV[threadIdx.x] = velocity[threadIdx.x];
        sA[threadIdx.x] = angles[threadIdx.x];
    }
    __syncthreads();

    const float cf = __ldg(coeff);
    const float bs = __ldg(bias);

    int idx = blockIdx.x * THREADS + threadIdx.x;
    if (idx >= TOTAL4) return;

    float4 d4 = __ldg(&data[idx]);
    float v[4] = {d4.x, d4.y, d4.z, d4.w};

    #pragma unroll
    for (int lane = 0; lane < 4; ++lane) {
        float d = v[lane];
        #pragma unroll
        for (int s = 0; s < NSTEPS; ++s) {
            float t     = tanh_fast(d * cf + bs);
            // reference: 1.0 + tanh/2.0 * NUM_POINTS
            float index = 1.0f + t * 0.5f * (float)NP;
            int   bgn   = (int)floorf(index);
            int   end   = (int)floorf(index + 1.0f);
            // reference clamp (end < NP else shift both down)
            if (end >= NP) { bgn -= 1; end -= 1; }
            float pos = index - (float)bgn;
            int bw = (bgn < 0) ? bgn + NP : bgn;
            int ew = (end < 0) ? end + NP : end;
            float om   = 1.0f - pos;
            float velo = om * sV[bw] + pos * sV[ew];
            float ang  = om * sA[bw] + pos * sA[ew];
            float sn, cs;
            __sincosf(ang, &sn, &cs);
            float step = velo * cs + d * velo * sn;
            d = d + step * (1.0f / (float)NSTEPS);
        }
        v[lane] = d;
    }

    // channel block within row: c4 in [0,128); input channels 4*c4..4*c4+3
    int c4 = idx & (IN_CH / 4 - 1);
    int b  = idx >> 7;                       // idx / 128

    // output channels oc = 2*c + f for f in {0,1}; 8 contiguous floats = 2 float4
    const float4* att4 = (const float4*)attention;
    float4 a0 = __ldg(&att4[2 * c4]);
    float4 a1 = __ldg(&att4[2 * c4 + 1]);

    float4 o0 = make_float4(a0.x * v[0], a0.y * v[0], a0.z * v[1], a0.w * v[1]);
    float4 o1 = make_float4(a1.x * v[2], a1.y * v[2], a1.z * v[3], a1.w * v[3]);

    int base = b * (OUT_CH / 4) + 2 * c4;    // out as float4 array, row stride 256
    out[base]     = o0;
    out[base + 1] = o1;
}

extern "C" void kernel_launch(void* const* d_in, const int* in_sizes, int n_in,
                              void* d_out, int out_size)
{
    const float4* data      = (const float4*)d_in[0];
    const float*  angles    = (const float*)d_in[1];
    const float*  velocity  = (const float*)d_in[2];
    const float*  attention = (const float*)d_in[3];
    const float*  coeff     = (const float*)d_in[4];
    const float*  bias      = (const float*)d_in[5];
    float4*       out       = (float4*)d_out;

    dim3 grid(TOTAL4 / THREADS);
    macunit_kernel<<<grid, THREADS>>>(data, angles, velocity, attention,
                                      coeff, bias, out);
}

// round 2
// speedup vs baseline: 1.4773x; 1.4773x over previous
#include <cuda_runtime.h>
#include <cuda_bf16.h>

#define BATCH       32768
#define IN_CH       512
#define OUT_CH      1024
#define NP          17
#define NSTEPS      3

#define TOTAL4      (BATCH * IN_CH / 4)     // 4,194,304 threads
#define THREADS     256

__device__ __forceinline__ float f_ex2(float x){ float r; asm("ex2.approx.f32 %0,%1;" : "=f"(r) : "f"(x)); return r; }
__device__ __forceinline__ float f_rcp(float x){ float r; asm("rcp.approx.f32 %0,%1;" : "=f"(r) : "f"(x)); return r; }
__device__ __forceinline__ float f_sin(float x){ float r; asm("sin.approx.f32 %0,%1;" : "=f"(r) : "f"(x)); return r; }
__device__ __forceinline__ float f_cos(float x){ float r; asm("cos.approx.f32 %0,%1;" : "=f"(r) : "f"(x)); return r; }

__global__ void __launch_bounds__(THREADS)
macunit_kernel(const float4* __restrict__ data,
               const float*  __restrict__ angles,
               const float*  __restrict__ velocity,
               const float*  __restrict__ attention,
               const float*  __restrict__ coeff,
               const float*  __restrict__ bias,
               float4*       __restrict__ out)
{
    // Extended knot table: for m = floor(index)+8 in [0,17],
    //   bgn_w = m<=7 ? m+9 : m-8   (torch negative-wrap folded in)
    //   end_w = m<=6 ? m+10 : m-7
    // entry = {vel[bgn_w], vel[end_w], ang[bgn_w], ang[end_w]}
    __shared__ float4 sT[18];
    if (threadIdx.x < 18) {
        int m  = threadIdx.x;
        int bw = (m <= 7) ? m + 9  : m - 8;
        int ew = (m <= 6) ? m + 10 : m - 7;
        sT[m] = make_float4(velocity[bw], velocity[ew], angles[bw], angles[ew]);
    }
    __syncthreads();

    // e^(2*(cf*d+bs)) = 2^(K1*d + K2)
    const float cf = __ldg(coeff);
    const float bs = __ldg(bias);
    const float K1 = 2.0f * cf * 1.4426950408889634f;
    const float K2 = 2.0f * bs * 1.4426950408889634f;

    int idx = blockIdx.x * THREADS + threadIdx.x;
    if (idx >= TOTAL4) return;

    float4 d4 = __ldg(&data[idx]);
    float v[4] = {d4.x, d4.y, d4.z, d4.w};

    #pragma unroll
    for (int lane = 0; lane < 4; ++lane) {
        float d = v[lane];
        #pragma unroll
        for (int s = 0; s < NSTEPS; ++s) {
            // z = index + 8 = 17.5 - 17/(1+e^{2(cf*d+bs)})  in [0.5, 17.5)
            float e = f_ex2(fmaf(d, K1, K2));
            float r = f_rcp(e + 1.0f);
            float z = fmaf(r, -17.0f, 17.5f);
            int   m = (int)z;                 // trunc == floor (z > 0)
            float pos = z - (float)m;
            float4 t = sT[m];                 // {v0, v1, a0, a1}
            float velo = fmaf(pos, t.y - t.x, t.x);
            float ang  = fmaf(pos, t.w - t.z, t.z);
            float sn = f_sin(ang);
            float cs = f_cos(ang);
            float vs = velo * sn;
            float vc = velo * cs;
            float st = fmaf(d, vs, vc);       // velo*cos + d*velo*sin
            d = fmaf(st, 0.33333333333333333f, d);
        }
        v[lane] = d;
    }

    int c4 = idx & (IN_CH / 4 - 1);          // channel-quad within row
    int b  = idx >> 7;                       // batch row

    const float4* att4 = (const float4*)attention;
    float4 a0 = __ldg(&att4[2 * c4]);
    float4 a1 = __ldg(&att4[2 * c4 + 1]);

    float4 o0 = make_float4(a0.x * v[0], a0.y * v[0], a0.z * v[1], a0.w * v[1]);
    float4 o1 = make_float4(a1.x * v[2], a1.y * v[2], a1.z * v[3], a1.w * v[3]);

    int base = b * (OUT_CH / 4) + 2 * c4;
    out[base]     = o0;
    out[base + 1] = o1;
}

extern "C" void kernel_launch(void* const* d_in, const int* in_sizes, int n_in,
                              void* d_out, int out_size)
{
    const float4* data      = (const float4*)d_in[0];
    const float*  angles    = (const float*)d_in[1];
    const float*  velocity  = (const float*)d_in[2];
    const float*  attention = (const float*)d_in[3];
    const float*  coeff     = (const float*)d_in[4];
    const float*  bias      = (const float*)d_in[5];
    float4*       out       = (float4*)d_out;

    dim3 grid(TOTAL4 / THREADS);
    macunit_kernel<<<grid, THREADS>>>(data, angles, velocity, attention,
                                      coeff, bias, out);
}